// round 5
// baseline (speedup 1.0000x reference)
#include <cuda_runtime.h>
#include <stdint.h>

#define NANCH 9
#define NPIX  1024
#define NBOX  9216          // NPIX * NANCH
#define NWORDS 144          // ceil(NBOX/64)
#define SORT_CAP 16384
#define W1ELEMS (9*1280*256)

// packed f32x2 FMA (full-rate fp32 path on sm_103a)
#define FMA2(acc, a, b) asm("fma.rn.f32x2 %0, %1, %2, %0;" : "+l"(acc) : "l"(a), "l"(b))

// ---------------- device scratch ----------------
__device__ float g_w1t[W1ELEMS];                 // w1 repacked [tap][c][oc]
__device__ float g_hp[9][256 * NPIX];            // conv1 partial sums per tap
__device__ float g_h[256 * NPIX];                // activated hidden
__device__ float g_boxes[NBOX * 4];
__device__ float g_conf[NBOX];
__device__ unsigned long long g_items[SORT_CAP]; // (~conf_bits<<32)|idx
__device__ int g_count;
__device__ unsigned long long g_mask[(size_t)NBOX * NWORDS];
__device__ unsigned char g_keep[NBOX];

__global__ void k_dummy() {}

// ---------------- repack w1 (coalesced reads, scattered stores) + init ----------------
__global__ void k_repack(const float* __restrict__ w1) {
    int i = blockIdx.x * 256 + threadIdx.x;
    // fold init
    if (i < SORT_CAP) g_items[i] = ~0ULL;
    if (i < NBOX)     g_keep[i] = 0;
    if (i == 0)       g_count = 0;
    if (i >= W1ELEMS) return;
    int o  = i / 11520;          // 1280*9
    int r  = i - o * 11520;
    int c  = r / 9;
    int tp = r - c * 9;
    g_w1t[tp * (1280 * 256) + c * 256 + o] = w1[i];
}

// ---------------- conv1: per-tap 128oc x 64px tile, 2 blocks/SM, f32x2 ----------------
// grid (2, 16, 9), 256 threads, 8 oc x 4 px per thread, K-tile 16
__global__ void __launch_bounds__(256) k_conv1(const float* __restrict__ feat) {
    __shared__ float As[2][16][256];   // [buf][k][oc duplicated pairs]
    __shared__ float Bs[2][16][64];    // [buf][k][px]

    const int ocBase = blockIdx.x * 128;
    const int p0     = blockIdx.y * 64;
    const int tp     = blockIdx.z;
    const int dy = tp / 3 - 1, dx = tp % 3 - 1;
    const int sh = dy * 32 + dx;

    const int tid = threadIdx.x;
    // A loader: 2 x float4 per thread (rows arow, arow+8)
    const int arow = tid >> 5;          // 0..7
    const int acol = (tid & 31) * 4;
    // B loader: 4 scalars per thread (rows brow+{0,4,8,12}), coalesced px
    const int bpx  = tid & 63;
    const int brow = tid >> 6;          // 0..3
    const int p    = p0 + bpx;
    const int yy   = (p >> 5) + dy;
    const int xx   = (p & 31) + dx;
    const bool bok = ((unsigned)yy < 32u) && ((unsigned)xx < 32u);
    const int bsrc = p + sh;

    const float* wp = g_w1t + (size_t)tp * (1280 * 256) + ocBase;

    // compute mapping: 16x16 thread grid, 8 oc x 4 px
    const int ty = tid >> 4;   // 0..15
    const int tx = tid & 15;   // 0..15

    unsigned long long acc[8][2];
#pragma unroll
    for (int i = 0; i < 8; i++) { acc[i][0] = 0ull; acc[i][1] = 0ull; }

    float4 a_reg0, a_reg1;
    float  b_reg[4];

    a_reg0 = *(const float4*)(wp + arow * 256 + acol);
    a_reg1 = *(const float4*)(wp + (arow + 8) * 256 + acol);
#pragma unroll
    for (int i = 0; i < 4; i++) {
        int c = brow + i * 4;
        b_reg[i] = bok ? feat[c * 1024 + bsrc] : 0.f;
    }

    int buf = 0;
    for (int c0 = 0; c0 < 1280; c0 += 16) {
        // store A duplicated: (x,x,y,y),(z,z,w,w)
        *(float4*)&As[buf][arow][acol * 2]         = make_float4(a_reg0.x, a_reg0.x, a_reg0.y, a_reg0.y);
        *(float4*)&As[buf][arow][acol * 2 + 4]     = make_float4(a_reg0.z, a_reg0.z, a_reg0.w, a_reg0.w);
        *(float4*)&As[buf][arow + 8][acol * 2]     = make_float4(a_reg1.x, a_reg1.x, a_reg1.y, a_reg1.y);
        *(float4*)&As[buf][arow + 8][acol * 2 + 4] = make_float4(a_reg1.z, a_reg1.z, a_reg1.w, a_reg1.w);
#pragma unroll
        for (int i = 0; i < 4; i++) Bs[buf][brow + i * 4][bpx] = b_reg[i];
        __syncthreads();

        if (c0 + 16 < 1280) {
            const int cn = c0 + 16;
            a_reg0 = *(const float4*)(wp + (cn + arow) * 256 + acol);
            a_reg1 = *(const float4*)(wp + (cn + arow + 8) * 256 + acol);
#pragma unroll
            for (int i = 0; i < 4; i++) {
                int c = cn + brow + i * 4;
                b_reg[i] = bok ? feat[c * 1024 + bsrc] : 0.f;
            }
        }

#pragma unroll
        for (int kk = 0; kk < 16; ++kk) {
            // 8 duplicated oc pairs = 4 x LDS.128
            ulonglong2 da = *(const ulonglong2*)&As[buf][kk][ty * 16];
            ulonglong2 db = *(const ulonglong2*)&As[buf][kk][ty * 16 + 4];
            ulonglong2 dc = *(const ulonglong2*)&As[buf][kk][ty * 16 + 8];
            ulonglong2 dd = *(const ulonglong2*)&As[buf][kk][ty * 16 + 12];
            ulonglong2 bq = *(const ulonglong2*)&Bs[buf][kk][tx * 4];
            FMA2(acc[0][0], da.x, bq.x); FMA2(acc[0][1], da.x, bq.y);
            FMA2(acc[1][0], da.y, bq.x); FMA2(acc[1][1], da.y, bq.y);
            FMA2(acc[2][0], db.x, bq.x); FMA2(acc[2][1], db.x, bq.y);
            FMA2(acc[3][0], db.y, bq.x); FMA2(acc[3][1], db.y, bq.y);
            FMA2(acc[4][0], dc.x, bq.x); FMA2(acc[4][1], dc.x, bq.y);
            FMA2(acc[5][0], dc.y, bq.x); FMA2(acc[5][1], dc.y, bq.y);
            FMA2(acc[6][0], dd.x, bq.x); FMA2(acc[6][1], dd.x, bq.y);
            FMA2(acc[7][0], dd.y, bq.x); FMA2(acc[7][1], dd.y, bq.y);
        }
        buf ^= 1;
    }

    const int oc = ocBase + ty * 8;
    const int px = p0 + tx * 4;
#pragma unroll
    for (int i = 0; i < 8; i++) {
        float* dst = g_hp[tp] + (size_t)(oc + i) * 1024 + px;
        *(unsigned long long*)(dst)     = acc[i][0];
        *(unsigned long long*)(dst + 2) = acc[i][1];
    }
}

// ---------------- combine 9 partials + bias + leaky relu (float4) ----------------
__global__ void __launch_bounds__(256) k_act(const float* __restrict__ b1) {
    int i = blockIdx.x * 256 + threadIdx.x;   // 65536 float4s
    const float4* h0 = (const float4*)g_hp[0];
    float4 v = h0[i];
#pragma unroll
    for (int z = 1; z < 9; z++) {
        float4 t = ((const float4*)g_hp[z])[i];
        v.x += t.x; v.y += t.y; v.z += t.z; v.w += t.w;
    }
    float b = b1[i >> 8];
    v.x += b; v.y += b; v.z += b; v.w += b;
    v.x = (v.x > 0.f) ? v.x : 0.01f * v.x;
    v.y = (v.y > 0.f) ? v.y : 0.01f * v.y;
    v.z = (v.z > 0.f) ? v.z : 0.01f * v.z;
    v.w = (v.w > 0.f) ? v.w : 0.01f * v.w;
    ((float4*)g_h)[i] = v;
}

// ---------------- conv2 (1x1) + sigmoid + decode + compaction ----------------
__global__ void __launch_bounds__(64) k_conv2(const float* __restrict__ w2,
                                              const float* __restrict__ b2,
                                              const float* __restrict__ anch) {
    __shared__ float sw[5][256];
    const int t = blockIdx.x * 64 + threadIdx.x;
    const int a = t >> 10;
    const int p = t & 1023;
    const int F[5] = {0, 2, 3, 4, 5};
#pragma unroll
    for (int f = 0; f < 5; ++f)
        for (int c = threadIdx.x; c < 256; c += 64)
            sw[f][c] = w2[(a * 6 + F[f]) * 256 + c];
    __syncthreads();
    float s0 = 0.f, s1 = 0.f, s2 = 0.f, s3 = 0.f, s4 = 0.f;
#pragma unroll 4
    for (int cc = 0; cc < 256; ++cc) {
        float hv = g_h[cc * 1024 + p];
        s0 = fmaf(sw[0][cc], hv, s0);
        s1 = fmaf(sw[1][cc], hv, s1);
        s2 = fmaf(sw[2][cc], hv, s2);
        s3 = fmaf(sw[3][cc], hv, s3);
        s4 = fmaf(sw[4][cc], hv, s4);
    }
    float logit = s0 + b2[a * 6 + 0];
    float tx = s1 + b2[a * 6 + 2];
    float ty = s2 + b2[a * 6 + 3];
    float tw = s3 + b2[a * 6 + 4];
    float th = s4 + b2[a * 6 + 5];
    float aw = anch[a * 2 + 0], ah = anch[a * 2 + 1];
    float cx = (float)(p & 31) + 0.5f;
    float cy = (float)(p >> 5) + 0.5f;
    float pcx = cx + tx * aw;
    float pcy = cy + ty * ah;
    float pw = aw * expf(tw);
    float ph = ah * expf(th);
    float conf = 1.0f / (1.0f + expf(-logit));
    int r = p * 9 + a;
    g_boxes[r * 4 + 0] = pcx - pw * 0.5f;
    g_boxes[r * 4 + 1] = pcy - ph * 0.5f;
    g_boxes[r * 4 + 2] = pcx + pw * 0.5f;
    g_boxes[r * 4 + 3] = pcy + ph * 0.5f;
    g_conf[r] = conf;
    if (conf > 0.5f) {
        int j = atomicAdd(&g_count, 1);
        unsigned int sb = __float_as_uint(conf);
        g_items[j] = ((unsigned long long)(~sb) << 32) | (unsigned int)r;
    }
}

// ---------------- bitonic sort (ascending), 4096-elem shared chunks ----------------
__global__ void __launch_bounds__(1024) k_sort_local4k() {
    __shared__ unsigned long long s[4096];
    const int base = blockIdx.x * 4096;
    const int tid = threadIdx.x;
#pragma unroll
    for (int e = 0; e < 4; e++) s[tid + e * 1024] = g_items[base + tid + e * 1024];
    __syncthreads();
    for (int k = 2; k <= 4096; k <<= 1) {
        for (int j = k >> 1; j > 0; j >>= 1) {
#pragma unroll
            for (int e = 0; e < 2; e++) {
                int t = tid + e * 1024;
                int i = ((t & ~(j - 1)) << 1) | (t & (j - 1));
                int l = i + j;
                bool up = (((base + i) & k) == 0);
                unsigned long long x = s[i], y = s[l];
                if (up ? (x > y) : (x < y)) { s[i] = y; s[l] = x; }
            }
            __syncthreads();
        }
    }
#pragma unroll
    for (int e = 0; e < 4; e++) g_items[base + tid + e * 1024] = s[tid + e * 1024];
}

// minN: skip phase if all data already confined+sorted (suffix = max keys)
__global__ void __launch_bounds__(1024) k_sort_global(int k, int j, int minN) {
    if (g_count <= minN) return;
    int t = blockIdx.x * 1024 + threadIdx.x;
    int i = ((t & ~(j - 1)) << 1) | (t & (j - 1));
    int l = i + j;
    bool up = ((i & k) == 0);
    unsigned long long x = g_items[i], y = g_items[l];
    if (up ? (x > y) : (x < y)) { g_items[i] = y; g_items[l] = x; }
}

__global__ void __launch_bounds__(1024) k_sort_finish4k(int k, int minN) {
    if (g_count <= minN) return;
    __shared__ unsigned long long s[4096];
    const int base = blockIdx.x * 4096;
    const int tid = threadIdx.x;
#pragma unroll
    for (int e = 0; e < 4; e++) s[tid + e * 1024] = g_items[base + tid + e * 1024];
    __syncthreads();
    for (int j = 2048; j > 0; j >>= 1) {
#pragma unroll
        for (int e = 0; e < 2; e++) {
            int t = tid + e * 1024;
            int i = ((t & ~(j - 1)) << 1) | (t & (j - 1));
            int l = i + j;
            bool up = (((base + i) & k) == 0);
            unsigned long long x = s[i], y = s[l];
            if (up ? (x > y) : (x < y)) { s[i] = y; s[l] = x; }
        }
        __syncthreads();
    }
#pragma unroll
    for (int e = 0; e < 4; e++) g_items[base + tid + e * 1024] = s[tid + e * 1024];
}

// ---------------- NMS bitmask build ----------------
__global__ void __launch_bounds__(64) k_mask() {
    const int n = g_count;
    const int rb = blockIdx.y, cb = blockIdx.x;
    if (cb < rb) return;
    if (rb * 64 >= n) return;
    if (cb * 64 >= n) return;
    __shared__ float4 sbox[64];
    const int tid = threadIdx.x;
    const int col0 = cb * 64;
    if (col0 + tid < n) {
        int r = (unsigned int)g_items[col0 + tid];
        sbox[tid] = *(const float4*)&g_boxes[r * 4];
    }
    __syncthreads();
    const int row = rb * 64 + tid;
    if (row >= n) return;
    int rr = (unsigned int)g_items[row];
    float4 bi = *(const float4*)&g_boxes[rr * 4];
    float areai = fmaxf(bi.z - bi.x, 0.f) * fmaxf(bi.w - bi.y, 0.f);
    unsigned long long bits = 0;
    int jmax = min(64, n - col0);
    for (int jj = 0; jj < jmax; ++jj) {
        int col = col0 + jj;
        if (col <= row) continue;
        float4 bj = sbox[jj];
        float iw = fmaxf(fminf(bi.z, bj.z) - fmaxf(bi.x, bj.x), 0.f);
        float ih = fmaxf(fminf(bi.w, bj.w) - fmaxf(bi.y, bj.y), 0.f);
        float inter = iw * ih;
        float areaj = fmaxf(bj.z - bj.x, 0.f) * fmaxf(bj.w - bj.y, 0.f);
        float iou = inter / (areai + areaj - inter + 1e-8f);
        if (iou > 0.7f) bits |= (1ull << jj);
    }
    g_mask[(size_t)row * NWORDS + cb] = bits;
}

// ---------------- greedy NMS reduce: ffs chain + diag prefetch ----------------
__global__ void __launch_bounds__(256) k_reduce() {
    __shared__ unsigned long long s_remv[NWORDS];
    __shared__ unsigned long long s_diag[2][64];
    __shared__ unsigned long long s_keepw;
    const int n = g_count;
    const int nb = (n + 63) >> 6;
    const int tid = threadIdx.x;
    for (int i = tid; i < NWORDS; i += 256) s_remv[i] = 0;
    if (tid < 64) s_diag[0][tid] = (tid < n) ? g_mask[(size_t)tid * NWORDS] : 0ULL;
    __syncthreads();
    const int q   = tid & 3;
    const int off = tid >> 2;
    for (int w = 0; w < nb; ++w) {
        const int pb = w & 1;
        if (tid >= 64 && tid < 128) {
            int t2 = tid - 64;
            int w1 = w + 1;
            if (w1 < nb) {
                int row = w1 * 64 + t2;
                s_diag[pb ^ 1][t2] = (row < n) ? g_mask[(size_t)row * NWORDS + w1] : 0ULL;
            }
        }
        if (tid == 0) {
            unsigned long long cur = s_remv[w];
            int rem = n - w * 64;
            if (rem < 64) cur |= (~0ULL) << rem;
            unsigned long long keepw = 0;
            unsigned long long alive = ~cur;
            while (alive) {
                int b = __ffsll((long long)alive) - 1;
                keepw |= 1ULL << b;
                cur |= s_diag[pb][b];
                alive = (~cur) & ~((2ULL << b) - 1ULL);
            }
            s_keepw = keepw;
        }
        __syncthreads();
        const unsigned long long kw = s_keepw;
        for (int w2 = w + 1 + off; w2 < nb; w2 += 64) {
            unsigned long long accv = 0;
#pragma unroll
            for (int bb = 0; bb < 16; ++bb) {
                int b = q * 16 + bb;
                if ((kw >> b) & 1ULL)
                    accv |= g_mask[(size_t)(w * 64 + b) * NWORDS + w2];
            }
            if (accv) atomicOr(&s_remv[w2], accv);
        }
        if (tid >= 128 && tid < 192) {
            int t2 = tid - 128;
            if ((kw >> t2) & 1ULL) {
                int r = (unsigned int)g_items[w * 64 + t2];
                g_keep[r] = 1;
            }
        }
        __syncthreads();
    }
}

// ---------------- final output ----------------
__global__ void __launch_bounds__(256) k_output(float* __restrict__ out) {
    int i = blockIdx.x * 256 + threadIdx.x;
    if (i >= NBOX) return;
    float k = g_keep[i] ? 1.0f : 0.0f;
    float4 b = *(const float4*)&g_boxes[i * 4];
    out[i * 5 + 0] = b.x * k;
    out[i * 5 + 1] = b.y * k;
    out[i * 5 + 2] = b.z * k;
    out[i * 5 + 3] = b.w * k;
    out[i * 5 + 4] = g_conf[i] * k;
}

// ---------------- launch ----------------
extern "C" void kernel_launch(void* const* d_in, const int* in_sizes, int n_in,
                              void* d_out, int out_size) {
    const float *feat = nullptr, *anch = nullptr, *w1 = nullptr,
                *b1 = nullptr, *w2 = nullptr, *b2 = nullptr;
    for (int i = 0; i < n_in; ++i) {
        switch (in_sizes[i]) {
            case 1310720: feat = (const float*)d_in[i]; break;
            case 18:      anch = (const float*)d_in[i]; break;
            case 2949120: w1   = (const float*)d_in[i]; break;
            case 256:     b1   = (const float*)d_in[i]; break;
            case 13824:   w2   = (const float*)d_in[i]; break;
            case 54:      b2   = (const float*)d_in[i]; break;
            default: break;
        }
    }
    float* out = (float*)d_out;

    k_repack<<<(W1ELEMS + 255) / 256, 256>>>(w1); // 0 (init folded in)
    k_dummy<<<1, 32>>>();                          // 1
    k_dummy<<<1, 32>>>();                          // 2
    k_conv1<<<dim3(2, 16, 9), 256>>>(feat);        // 3 <- ncu capture slot
    k_act<<<256, 256>>>(b1);                       // 4
    k_conv2<<<144, 64>>>(w2, b2, anch);            // 5

    k_sort_local4k<<<4, 1024>>>();
    k_sort_global<<<8, 1024>>>(8192, 4096, 4096);
    k_sort_finish4k<<<4, 1024>>>(8192, 4096);
    k_sort_global<<<8, 1024>>>(16384, 8192, 8192);
    k_sort_global<<<8, 1024>>>(16384, 4096, 8192);
    k_sort_finish4k<<<4, 1024>>>(16384, 8192);

    k_mask<<<dim3(NWORDS, NWORDS), 64>>>();
    k_reduce<<<1, 256>>>();
    k_output<<<36, 256>>>(out);
}